// round 1
// baseline (speedup 1.0000x reference)
#include <cuda_runtime.h>
#include <math.h>

// Problem constants (fixed shapes from setup_inputs)
#define T_  16
#define B_  16
#define C_  8
#define H_  128
#define W_  128
#define HW_ (H_ * W_)      // 16384
#define CHW_ (C_ * HW_)    // 131072
#define TB_ (T_ * B_)      // 256

// Scratch for per-(t,b[,c]) scalars computed by stats pass
__device__ float g_beta[TB_ * C_];
__device__ float g_thr[TB_];

// ---------------------------------------------------------------------------
// Kernel 1: per-(t,b) statistics -> beta[t,b,c], thr[t,b]
//   one block per (t,b), 256 threads, dynamic smem = y[H*W] (64 KB)
// ---------------------------------------------------------------------------
__global__ __launch_bounds__(256) void stats_kernel(
    const float* __restrict__ events,
    const float* __restrict__ att_w1,     // (1, 2C) row-major: [mx_0..mx_7, av_0..av_7]
    const float* __restrict__ att_w2,     // (C, 1)
    const float* __restrict__ density_w,  // scalar
    const float* __restrict__ temporal_w, // scalar
    const float* __restrict__ motion_w)   // scalar
{
    extern __shared__ float s_y[];        // y(h,w) = sum_c x(c,h,w), HW floats
    __shared__ float s_red[8][20];        // cross-warp staging (8 warps x 19 vals)

    const int tb  = blockIdx.x;           // tb = t*B + b
    const int t   = tb / B_;
    const int tid = threadIdx.x;

    const float* __restrict__ cur  = events + (size_t)tb * CHW_;
    const float* __restrict__ prev = cur - (size_t)B_ * CHW_;   // valid iff t>0

    float chmax[C_], chsum[C_];
#pragma unroll
    for (int c = 0; c < C_; c++) { chmax[c] = -3.4e38f; chsum[c] = 0.f; }
    float dsum = 0.f;   // sum |x_t - x_{t-1}|
    float wsq  = 0.f;   // sum x^2 * cnt(h)*cnt(w)   ( == sum_hw s2 )

    // ---- pass 1: per-element stats + channel-summed image y ----
    for (int i = tid; i < HW_; i += 256) {
        const int h = i >> 7;
        const int w = i & (W_ - 1);
        const float cnt = ((h == 0 || h == H_ - 1) ? 2.f : 3.f) *
                          ((w == 0 || w == W_ - 1) ? 2.f : 3.f);
        float ysum = 0.f;
#pragma unroll
        for (int c = 0; c < C_; c++) {
            const float v = cur[c * HW_ + i];
            ysum += v;
            chsum[c] += v;
            chmax[c] = fmaxf(chmax[c], v);
            wsq += cnt * v * v;
            if (t > 0) {
                dsum += fabsf(v - prev[c * HW_ + i]);
            }
        }
        s_y[i] = ysum;
    }

    // warp-level tree reduction of the 18 pass-1 accumulators
#pragma unroll
    for (int off = 16; off; off >>= 1) {
#pragma unroll
        for (int c = 0; c < C_; c++) {
            chsum[c] += __shfl_down_sync(0xffffffffu, chsum[c], off);
            chmax[c]  = fmaxf(chmax[c], __shfl_down_sync(0xffffffffu, chmax[c], off));
        }
        dsum += __shfl_down_sync(0xffffffffu, dsum, off);
        wsq  += __shfl_down_sync(0xffffffffu, wsq,  off);
    }

    __syncthreads();   // s_y complete

    // ---- pass 2: s1 = 3x3 zero-padded box sum of y; accumulate s1^2 ----
    float s1sq = 0.f;
    for (int i = tid; i < HW_; i += 256) {
        const int h = i >> 7;
        const int w = i & (W_ - 1);
        float s1 = 0.f;
#pragma unroll
        for (int dh = -1; dh <= 1; dh++) {
            const int hh = h + dh;
            if (hh < 0 || hh >= H_) continue;
            const float* row = &s_y[hh * W_];
#pragma unroll
            for (int dw = -1; dw <= 1; dw++) {
                const int ww = w + dw;
                if (ww < 0 || ww >= W_) continue;
                s1 += row[ww];
            }
        }
        s1sq += s1 * s1;
    }
#pragma unroll
    for (int off = 16; off; off >>= 1)
        s1sq += __shfl_down_sync(0xffffffffu, s1sq, off);

    const int wid  = tid >> 5;
    const int lane = tid & 31;
    if (lane == 0) {
#pragma unroll
        for (int c = 0; c < C_; c++) {
            s_red[wid][c]      = chsum[c];
            s_red[wid][8 + c]  = chmax[c];
        }
        s_red[wid][16] = dsum;
        s_red[wid][17] = wsq;
        s_red[wid][18] = s1sq;
    }
    __syncthreads();

    if (tid == 0) {
        float csum[C_], cmax[C_];
#pragma unroll
        for (int c = 0; c < C_; c++) { csum[c] = 0.f; cmax[c] = -3.4e38f; }
        float tds = 0.f, twsq = 0.f, ts1 = 0.f;
        for (int wgi = 0; wgi < 8; wgi++) {
#pragma unroll
            for (int c = 0; c < C_; c++) {
                csum[c] += s_red[wgi][c];
                cmax[c]  = fmaxf(cmax[c], s_red[wgi][8 + c]);
            }
            tds  += s_red[wgi][16];
            twsq += s_red[wgi][17];
            ts1  += s_red[wgi][18];
        }

        // tiny MLP: hidden = relu([mx, av] . w1), beta_c = 0.5 + 0.45*sigmoid(h * w2_c)
        float hpre = 0.f, tot = 0.f;
#pragma unroll
        for (int c = 0; c < C_; c++) {
            tot += csum[c];
            const float av = csum[c] * (1.f / HW_);
            hpre += cmax[c] * att_w1[c] + av * att_w1[C_ + c];
        }
        const float hid = fmaxf(hpre, 0.f);
#pragma unroll
        for (int c = 0; c < C_; c++) {
            const float z = hid * att_w2[c];
            g_beta[tb * C_ + c] = 0.5f + 0.45f / (1.f + expf(-z));
        }

        const float density  = tot * (1.f / CHW_);
        const float temporal = (t > 0) ? tds * (1.f / CHW_) : 0.f;
        // motion = mean_hw var,  var = (s2 - s1^2/72)/71,  sum_hw s2 == twsq
        const float motion = (twsq - ts1 * (1.f / 72.f)) * (1.f / (71.f * HW_));
        const float z = density_w[0] * density + temporal_w[0] * temporal
                      + motion_w[0] * motion;
        g_thr[tb] = 1.f + 2.f / (1.f + expf(-z));
    }
}

// ---------------------------------------------------------------------------
// Kernel 2: fused depthwise 3x3 conv + sequential LIF scan over T
//   block = (b, c, 32-row band); thread owns 16 pixels' membrane state in regs
// ---------------------------------------------------------------------------
#define BAND_ 32
#define NBANDS_ (H_ / BAND_)          // 4
#define TROWS_ (BAND_ + 2)            // 34

__global__ __launch_bounds__(256) void lif_kernel(
    const float* __restrict__ events,
    const float* __restrict__ conv_w,   // (C,1,3,3)
    float* __restrict__ out)
{
    __shared__ float tile[TROWS_ * W_];   // 34 x 128 = 17408 B

    const int band = blockIdx.x & (NBANDS_ - 1);
    const int bc   = blockIdx.x >> 2;
    const int c    = bc & (C_ - 1);
    const int b    = bc >> 3;
    const int h0   = band * BAND_;
    const int tid  = threadIdx.x;

    float K[9];
#pragma unroll
    for (int k = 0; k < 9; k++) K[k] = conv_w[c * 9 + k];

    float v[16];
#pragma unroll
    for (int k = 0; k < 16; k++) v[k] = 0.f;

    for (int t = 0; t < T_; t++) {
        const size_t plane = ((size_t)((t * B_ + b) * C_ + c)) * HW_;
        const float* __restrict__ ep = events + plane;

        // cooperative load of rows [h0-1, h0+32] with zero padding
        for (int j = tid; j < TROWS_ * W_; j += 256) {
            const int r = j >> 7;
            const int g = h0 - 1 + r;
            tile[j] = (g >= 0 && g < H_) ? ep[g * W_ + (j & (W_ - 1))] : 0.f;
        }
        __syncthreads();

        const float beta = g_beta[(t * B_ + b) * C_ + c];
        const float thr  = g_thr[t * B_ + b];
        const float omb  = 1.f - beta;
        float* __restrict__ op = out + plane + (size_t)h0 * W_;

#pragma unroll
        for (int k = 0; k < 16; k++) {
            const int p  = k * 256 + tid;      // 0..4095 within band
            const int hl = p >> 7;             // 0..31
            const int w  = p & (W_ - 1);
            const bool wl = (w > 0), wr = (w < W_ - 1);

            float wi = 0.f;
#pragma unroll
            for (int kh = 0; kh < 3; kh++) {
                const float* rr = &tile[(hl + kh) * W_];
                const float a = wl ? rr[w - 1] : 0.f;
                const float m = rr[w];
                const float bb = wr ? rr[w + 1] : 0.f;
                wi += K[kh * 3 + 0] * a + K[kh * 3 + 1] * m + K[kh * 3 + 2] * bb;
            }
            const float x  = tile[(hl + 1) * W_ + w];       // center = events value
            const float vv = beta * v[k] + omb * wi;        // charge
            const float spike = atanf(2.f * (vv - thr)) * 0.5f + 0.5f;  // fire
            op[p] = x * spike;
            v[k]  = (1.f - spike) * vv;                     // reset
        }
        __syncthreads();
    }
}

// ---------------------------------------------------------------------------
extern "C" void kernel_launch(void* const* d_in, const int* in_sizes, int n_in,
                              void* d_out, int out_size)
{
    const float* events     = (const float*)d_in[0];
    const float* conv_w     = (const float*)d_in[1];
    const float* att_w1     = (const float*)d_in[2];
    const float* att_w2     = (const float*)d_in[3];
    const float* density_w  = (const float*)d_in[4];
    const float* temporal_w = (const float*)d_in[5];
    const float* motion_w   = (const float*)d_in[6];
    float* out = (float*)d_out;

    // 64 KB dynamic smem for y(h,w); opt-in above 48 KB (idempotent, capture-safe)
    cudaFuncSetAttribute(stats_kernel,
                         cudaFuncAttributeMaxDynamicSharedMemorySize,
                         HW_ * (int)sizeof(float));

    stats_kernel<<<TB_, 256, HW_ * sizeof(float)>>>(
        events, att_w1, att_w2, density_w, temporal_w, motion_w);

    lif_kernel<<<B_ * C_ * NBANDS_, 256>>>(events, conv_w, out);
}

// round 2
// speedup vs baseline: 1.3058x; 1.3058x over previous
#include <cuda_runtime.h>
#include <math.h>

// Problem constants (fixed shapes from setup_inputs)
#define T_  16
#define B_  16
#define C_  8
#define H_  128
#define W_  128
#define HW_ (H_ * W_)      // 16384
#define CHW_ (C_ * HW_)    // 131072
#define TB_ (T_ * B_)      // 256

// ---- stats band decomposition ----
#define SB_   32                  // stats band rows
#define NSB_  (H_ / SB_)          // 4 bands
#define NPART_ 19                 // 8 chsum + 8 chmax + dsum + wsq + s1sq

// Scratch
__device__ float g_part[TB_ * NSB_ * NPART_];
__device__ float g_beta[TB_ * C_];
__device__ float g_thr[TB_];

// ---------------------------------------------------------------------------
// Kernel 1: per-(t,b,band) partial statistics
//   grid = TB_*NSB_ blocks, 256 threads, smem = y tile (34 x 128)
// ---------------------------------------------------------------------------
__global__ __launch_bounds__(256) void stats_part_kernel(
    const float* __restrict__ events)
{
    __shared__ float s_y[(SB_ + 2) * W_];   // 34 x 128 = 17408 B
    __shared__ float s_red[8][NPART_ + 1];

    const int band = blockIdx.x & (NSB_ - 1);
    const int tb   = blockIdx.x >> 2;       // tb = t*B + b
    const int t    = tb / B_;
    const int h0   = band * SB_;
    const int tid  = threadIdx.x;

    const float* __restrict__ cur  = events + (size_t)tb * CHW_;
    const float* __restrict__ prev = cur - (size_t)B_ * CHW_;   // valid iff t>0

    float chmax[C_], chsum[C_];
#pragma unroll
    for (int c = 0; c < C_; c++) { chmax[c] = -3.4e38f; chsum[c] = 0.f; }
    float dsum = 0.f;   // sum |x_t - x_{t-1}| over band
    float wsq  = 0.f;   // sum x^2 * cnt(h)*cnt(w) over band

    // ---- pass 1: y = sum_c x over band+halo rows; per-element stats in band
    const int NTOT = (SB_ + 2) * W_;        // 4352 = 17*256
#pragma unroll 1
    for (int j = tid; j < NTOT; j += 256) {
        const int r = j >> 7;               // tile row 0..33
        const int w = j & (W_ - 1);
        const int g = h0 - 1 + r;           // global row
        float ysum = 0.f;
        if (g >= 0 && g < H_) {
            const int gi = g * W_ + w;
            const bool inband = (r >= 1 && r <= SB_);
            const float cnt = ((g == 0 || g == H_ - 1) ? 2.f : 3.f) *
                              ((w == 0 || w == W_ - 1) ? 2.f : 3.f);
#pragma unroll
            for (int c = 0; c < C_; c++) {
                const float v = cur[c * HW_ + gi];
                ysum += v;
                if (inband) {
                    chsum[c] += v;
                    chmax[c] = fmaxf(chmax[c], v);
                    wsq += cnt * v * v;
                    if (t > 0) dsum += fabsf(v - prev[c * HW_ + gi]);
                }
            }
        }
        s_y[j] = ysum;
    }
    __syncthreads();

    // ---- pass 2: s1 = 3x3 zero-padded box sum of y; accumulate s1^2 in band
    float s1sq = 0.f;
#pragma unroll 1
    for (int p = tid; p < SB_ * W_; p += 256) {
        const int r = (p >> 7) + 1;         // tile row 1..32
        const int w = p & (W_ - 1);
        const bool wl = (w > 0), wr = (w < W_ - 1);
        float s1 = 0.f;
#pragma unroll
        for (int dr = -1; dr <= 1; dr++) {
            const float* row = &s_y[(r + dr) * W_];
            s1 += (wl ? row[w - 1] : 0.f) + row[w] + (wr ? row[w + 1] : 0.f);
        }
        s1sq += s1 * s1;
    }

    // warp tree reduction of 19 accumulators
#pragma unroll
    for (int off = 16; off; off >>= 1) {
#pragma unroll
        for (int c = 0; c < C_; c++) {
            chsum[c] += __shfl_down_sync(0xffffffffu, chsum[c], off);
            chmax[c]  = fmaxf(chmax[c], __shfl_down_sync(0xffffffffu, chmax[c], off));
        }
        dsum += __shfl_down_sync(0xffffffffu, dsum, off);
        wsq  += __shfl_down_sync(0xffffffffu, wsq,  off);
        s1sq += __shfl_down_sync(0xffffffffu, s1sq, off);
    }

    const int wid  = tid >> 5;
    const int lane = tid & 31;
    if (lane == 0) {
#pragma unroll
        for (int c = 0; c < C_; c++) {
            s_red[wid][c]     = chsum[c];
            s_red[wid][8 + c] = chmax[c];
        }
        s_red[wid][16] = dsum;
        s_red[wid][17] = wsq;
        s_red[wid][18] = s1sq;
    }
    __syncthreads();

    // first warp: reduce 8 partial rows (lane v owns value-index v)
    if (wid == 0 && lane < NPART_) {
        float acc = s_red[0][lane];
        if (lane >= 8 && lane < 16) {
#pragma unroll
            for (int k = 1; k < 8; k++) acc = fmaxf(acc, s_red[k][lane]);
        } else {
#pragma unroll
            for (int k = 1; k < 8; k++) acc += s_red[k][lane];
        }
        g_part[(blockIdx.x) * NPART_ + lane] = acc;
    }
}

// ---------------------------------------------------------------------------
// Kernel 2: finalize -> beta[t,b,c], thr[t,b]   (1 block, thread per tb)
// ---------------------------------------------------------------------------
__global__ __launch_bounds__(256) void stats_final_kernel(
    const float* __restrict__ att_w1,     // (1, 2C): [w_mx(8), w_av(8)]
    const float* __restrict__ att_w2,     // (C, 1)
    const float* __restrict__ density_w,
    const float* __restrict__ temporal_w,
    const float* __restrict__ motion_w)
{
    const int tb = threadIdx.x;
    const int t  = tb / B_;

    float csum[C_], cmax[C_];
#pragma unroll
    for (int c = 0; c < C_; c++) { csum[c] = 0.f; cmax[c] = -3.4e38f; }
    float tds = 0.f, twsq = 0.f, ts1 = 0.f;

#pragma unroll
    for (int bnd = 0; bnd < NSB_; bnd++) {
        const float* p = &g_part[(tb * NSB_ + bnd) * NPART_];
#pragma unroll
        for (int c = 0; c < C_; c++) {
            csum[c] += p[c];
            cmax[c]  = fmaxf(cmax[c], p[8 + c]);
        }
        tds += p[16]; twsq += p[17]; ts1 += p[18];
    }

    float hpre = 0.f, tot = 0.f;
#pragma unroll
    for (int c = 0; c < C_; c++) {
        tot += csum[c];
        hpre += cmax[c] * att_w1[c] + (csum[c] * (1.f / HW_)) * att_w1[C_ + c];
    }
    const float hid = fmaxf(hpre, 0.f);
#pragma unroll
    for (int c = 0; c < C_; c++) {
        const float z = hid * att_w2[c];
        g_beta[tb * C_ + c] = 0.5f + 0.45f / (1.f + expf(-z));
    }

    const float density  = tot * (1.f / CHW_);
    const float temporal = (t > 0) ? tds * (1.f / CHW_) : 0.f;
    const float motion   = (twsq - ts1 * (1.f / 72.f)) * (1.f / (71.f * HW_));
    const float z = density_w[0] * density + temporal_w[0] * temporal
                  + motion_w[0] * motion;
    g_thr[tb] = 1.f + 2.f / (1.f + expf(-z));
}

// ---------------------------------------------------------------------------
// Kernel 3: fused depthwise 3x3 conv + sequential LIF scan over T
//   block = (b, c, 16-row band); 1024 blocks; double-buffered via registers
// ---------------------------------------------------------------------------
#define BAND_ 16
#define NBANDS_ (H_ / BAND_)          // 8
#define TROWS_ (BAND_ + 2)            // 18
#define TSZ_ (TROWS_ * W_)            // 2304 = 9*256
#define PIX_ (BAND_ * W_ / 256)       // 8 pixels per thread

__global__ __launch_bounds__(256) void lif_kernel(
    const float* __restrict__ events,
    const float* __restrict__ conv_w,   // (C,1,3,3)
    float* __restrict__ out)
{
    __shared__ float tile[TSZ_];        // 18 x 128 = 9216 B

    const int band = blockIdx.x & (NBANDS_ - 1);
    const int bc   = blockIdx.x >> 3;
    const int c    = bc & (C_ - 1);
    const int b    = bc >> 3;
    const int h0   = band * BAND_;
    const int tid  = threadIdx.x;

    float K[9];
#pragma unroll
    for (int k = 0; k < 9; k++) K[k] = conv_w[c * 9 + k];

    float v[PIX_];
#pragma unroll
    for (int k = 0; k < PIX_; k++) v[k] = 0.f;

    // preload t=0 tile
    {
        const float* __restrict__ ep = events + ((size_t)(b * C_ + c)) * HW_;
#pragma unroll
        for (int k = 0; k < 9; k++) {
            const int j = k * 256 + tid;
            const int g = h0 - 1 + (j >> 7);
            tile[j] = (g >= 0 && g < H_) ? ep[g * W_ + (j & (W_ - 1))] : 0.f;
        }
    }
    __syncthreads();

#pragma unroll 1
    for (int t = 0; t < T_; t++) {
        // prefetch t+1 tile into registers (overlaps with compute below)
        float pf[9];
        if (t + 1 < T_) {
            const float* __restrict__ ep =
                events + ((size_t)(((t + 1) * B_ + b) * C_ + c)) * HW_;
#pragma unroll
            for (int k = 0; k < 9; k++) {
                const int j = k * 256 + tid;
                const int g = h0 - 1 + (j >> 7);
                pf[k] = (g >= 0 && g < H_) ? ep[g * W_ + (j & (W_ - 1))] : 0.f;
            }
        }

        const float beta = g_beta[(t * B_ + b) * C_ + c];
        const float thr  = g_thr[t * B_ + b];
        const float omb  = 1.f - beta;
        float* __restrict__ op =
            out + ((size_t)((t * B_ + b) * C_ + c)) * HW_ + (size_t)h0 * W_;

#pragma unroll
        for (int k = 0; k < PIX_; k++) {
            const int p  = k * 256 + tid;      // 0..2047 within band
            const int hl = p >> 7;             // 0..15
            const int w  = p & (W_ - 1);
            const bool wl = (w > 0), wr = (w < W_ - 1);

            float wi = 0.f;
#pragma unroll
            for (int kh = 0; kh < 3; kh++) {
                const float* rr = &tile[(hl + kh) * W_];
                wi += K[kh * 3 + 0] * (wl ? rr[w - 1] : 0.f)
                    + K[kh * 3 + 1] * rr[w]
                    + K[kh * 3 + 2] * (wr ? rr[w + 1] : 0.f);
            }
            const float x  = tile[(hl + 1) * W_ + w];       // center value
            const float vv = beta * v[k] + omb * wi;        // charge
            const float spike = atanf(2.f * (vv - thr)) * 0.5f + 0.5f;
            op[p] = x * spike;
            v[k]  = (1.f - spike) * vv;                     // reset
        }
        __syncthreads();
        if (t + 1 < T_) {
#pragma unroll
            for (int k = 0; k < 9; k++) tile[k * 256 + tid] = pf[k];
        }
        __syncthreads();
    }
}

// ---------------------------------------------------------------------------
extern "C" void kernel_launch(void* const* d_in, const int* in_sizes, int n_in,
                              void* d_out, int out_size)
{
    const float* events     = (const float*)d_in[0];
    const float* conv_w     = (const float*)d_in[1];
    const float* att_w1     = (const float*)d_in[2];
    const float* att_w2     = (const float*)d_in[3];
    const float* density_w  = (const float*)d_in[4];
    const float* temporal_w = (const float*)d_in[5];
    const float* motion_w   = (const float*)d_in[6];
    float* out = (float*)d_out;

    stats_part_kernel<<<TB_ * NSB_, 256>>>(events);
    stats_final_kernel<<<1, TB_>>>(att_w1, att_w2, density_w, temporal_w, motion_w);
    lif_kernel<<<B_ * C_ * NBANDS_, 256>>>(events, conv_w, out);
}